// round 16
// baseline (speedup 1.0000x reference)
#include <cuda_runtime.h>

// CRF forward (log partition) on GB300 — round 15.
// TWO batches per 32-thread CTA, packed into f32x2 lanes. Lane l = tag l.
// The smem exchange (the measured bottleneck: crossbar-bound at ~400 cy/step
// for one batch in R14) is shared by both batches: lane stores the pair
// (p0_l, p1_l) as one STS.64; split-K2 reads 16 pairs = 8 LDS.128 per lane.
// The matvec duplicates E into both f32x2 halves so each fma.rn.f32x2
// advances both batches: acc pair accumulates (acc0_i, acc1_i) directly.
// K-half combine: ONE 64-bit shfl_xor(.,16) per step (R11-verified mapping
// tau = r + 16*(h^k)). Exact pow2 rescale every 4 steps from the exponents
// of entry 0's pair (one broadcast LDS.64, off the critical path).

#define T_TAGS 32
#define START_TAG 30
#define STOP_TAG 31
#define LOG2E 1.4426950408889634f
#define LN2   0.6931471805599453f
#define PF 8   // emission prefetch depth per batch

__device__ __forceinline__ float ex2a(float x) {
    float r; asm("ex2.approx.f32 %0, %1;" : "=f"(r) : "f"(x)); return r;
}
__device__ __forceinline__ float lg2a(float x) {
    float r; asm("lg2.approx.f32 %0, %1;" : "=f"(r) : "f"(x)); return r;
}
__device__ __forceinline__ unsigned long long pk2(float lo, float hi) {
    unsigned long long r;
    asm("mov.b64 %0, {%1, %2};" : "=l"(r) : "f"(lo), "f"(hi));
    return r;
}
__device__ __forceinline__ void upk2(unsigned long long v, float& lo, float& hi) {
    asm("mov.b64 {%0, %1}, %2;" : "=f"(lo), "=f"(hi) : "l"(v));
}
__device__ __forceinline__ unsigned long long fma2(unsigned long long a,
                                                   unsigned long long b,
                                                   unsigned long long c) {
    unsigned long long d;
    asm("fma.rn.f32x2 %0, %1, %2, %3;" : "=l"(d) : "l"(a), "l"(b), "l"(c));
    return d;
}
__device__ __forceinline__ unsigned long long add2(unsigned long long a,
                                                   unsigned long long b) {
    unsigned long long d;
    asm("add.rn.f32x2 %0, %1, %2;" : "=l"(d) : "l"(a), "l"(b));
    return d;
}
__device__ __forceinline__ unsigned long long mul2(unsigned long long a,
                                                   unsigned long long b) {
    unsigned long long d;
    asm("mul.rn.f32x2 %0, %1, %2;" : "=l"(d) : "l"(a), "l"(b));
    return d;
}

// One recurrence step for the batch pair. buf is store target AND load source
// (BAR orders them; caller alternates buffers across steps).
template <bool RESCALE>
__device__ __forceinline__ void step2(
    float em0, float em1,
    unsigned long long& pp,          // packed (p0_lane, p1_lane)
    int& is0, int& is1,
    const unsigned long long (&E0)[16],   // dup'd exp(trans[lane][16h+m])
    const unsigned long long (&E1)[16],   // dup'd exp(trans[lane^16][16h+m])
    float* buf, int lane, int h)
{
    // emission factors — MUFU latency hides under the exchange
    float d0 = ex2a(em0 * LOG2E);
    float d1 = ex2a(em1 * LOG2E);

    *reinterpret_cast<unsigned long long*>(buf + 2 * lane) = pp;  // STS.64
    __syncthreads();   // 1-warp CTA: cheap BAR, drains the STS

    const ulonglong2* q = reinterpret_cast<const ulonglong2*>(buf + 32 * h);
    ulonglong2 v0 = q[0], v1 = q[1], v2 = q[2], v3 = q[3];
    ulonglong2 v4 = q[4], v5 = q[5], v6 = q[6], v7 = q[7];

    unsigned long long dd = pk2(d0, d1);
    if (RESCALE) {
        // entry 0's pair (identical broadcast read on all lanes)
        unsigned long long e0 = *reinterpret_cast<const unsigned long long*>(buf);
        float p00, p10;
        upk2(e0, p00, p10);
        int k0 = ((__float_as_int(p00) >> 23) & 0xff) - 127;
        int k1 = ((__float_as_int(p10) >> 23) & 0xff) - 127;
        is0 += k0; is1 += k1;
        unsigned long long rs = pk2(__int_as_float((127 - k0) << 23),
                                    __int_as_float((127 - k1) << 23));
        dd = mul2(dd, rs);   // fold exact 2^-k into the emission factor
    }

    // slot 0: row = lane; 4 chains of depth 4
    unsigned long long A, B, C, D;
    A = fma2(E0[0],  v0.x, 0ull);  B = fma2(E0[1],  v0.y, 0ull);
    C = fma2(E0[2],  v1.x, 0ull);  D = fma2(E0[3],  v1.y, 0ull);
    A = fma2(E0[4],  v2.x, A);     B = fma2(E0[5],  v2.y, B);
    C = fma2(E0[6],  v3.x, C);     D = fma2(E0[7],  v3.y, D);
    A = fma2(E0[8],  v4.x, A);     B = fma2(E0[9],  v4.y, B);
    C = fma2(E0[10], v5.x, C);     D = fma2(E0[11], v5.y, D);
    A = fma2(E0[12], v6.x, A);     B = fma2(E0[13], v6.y, B);
    C = fma2(E0[14], v7.x, C);     D = fma2(E0[15], v7.y, D);
    unsigned long long s0 = add2(add2(A, B), add2(C, D));

    // slot 1: row = lane^16
    unsigned long long A1, B1, C1, D1;
    A1 = fma2(E1[0],  v0.x, 0ull); B1 = fma2(E1[1],  v0.y, 0ull);
    C1 = fma2(E1[2],  v1.x, 0ull); D1 = fma2(E1[3],  v1.y, 0ull);
    A1 = fma2(E1[4],  v2.x, A1);   B1 = fma2(E1[5],  v2.y, B1);
    C1 = fma2(E1[6],  v3.x, C1);   D1 = fma2(E1[7],  v3.y, D1);
    A1 = fma2(E1[8],  v4.x, A1);   B1 = fma2(E1[9],  v4.y, B1);
    C1 = fma2(E1[10], v5.x, C1);   D1 = fma2(E1[11], v5.y, D1);
    A1 = fma2(E1[12], v6.x, A1);   B1 = fma2(E1[13], v6.y, B1);
    C1 = fma2(E1[14], v7.x, C1);   D1 = fma2(E1[15], v7.y, D1);
    unsigned long long s1 = add2(add2(A1, B1), add2(C1, D1));

    // partner (lane^16) computed the other K-half of MY row in its s1
    unsigned long long s1p = __shfl_xor_sync(0xffffffffu, s1, 16);
    unsigned long long acc = add2(s0, s1p);

    pp = mul2(acc, dd);
}

template <int SC>
__global__ __launch_bounds__(32, 8)
void crf_fwd_kernel(const float* __restrict__ feats,
                    const float* __restrict__ trans,
                    float* __restrict__ out,
                    int S_rt, int B) {
    const int S = (SC > 0) ? SC : S_rt;
    const int lane = threadIdx.x;
    const int h = lane >> 4;
    const int b0 = 2 * blockIdx.x;
    const int b1 = b0 + 1;
    const bool has_b1 = (b1 < B);

    __shared__ __align__(16) float sp[2][2 * T_TAGS];

    // ---- E in registers, duplicated into both f32x2 halves.
    //      Slot k covers row tau = lane with h-bit xor'd by k, columns
    //      [16h, 16h+16). E?[m] <-> entry j = 16h + m.
    unsigned long long E0[16], E1[16];
    {
        const float* t0 = trans + lane * T_TAGS + 16 * h;
        const float* t1 = trans + (lane ^ 16) * T_TAGS + 16 * h;
        #pragma unroll
        for (int m = 0; m < 16; m++) {
            float e0 = ex2a(t0[m] * LOG2E);
            float e1 = ex2a(t1[m] * LOG2E);
            E0[m] = pk2(e0, e0);
            E1[m] = pk2(e1, e1);
        }
    }

    // ---- Emission register pipelines (both batches) ----
    const float* f0 = feats + (size_t)b0 * (size_t)S * T_TAGS + lane;
    const float* f1 = has_b1 ? (feats + (size_t)b1 * (size_t)S * T_TAGS + lane) : f0;
    float eb0[PF], eb1[PF];
    #pragma unroll
    for (int k = 0; k < PF; k++) {
        eb0[k] = f0[(size_t)k * T_TAGS];
        eb1[k] = f1[(size_t)k * T_TAGS];
    }

    // ---- State: packed (p0, p1), one-hot at START; exact int shifts ----
    unsigned long long pp = (lane == START_TAG) ? pk2(1.0f, 1.0f) : 0ull;
    int is0 = 0, is1 = 0;

    if (SC == 512) {
        #pragma unroll 4
        for (int t = 0; t < 512 - PF; t++) {
            float em0 = eb0[t & (PF - 1)];
            float em1 = eb1[t & (PF - 1)];
            eb0[t & (PF - 1)] = f0[(size_t)(t + PF) * T_TAGS];
            eb1[t & (PF - 1)] = f1[(size_t)(t + PF) * T_TAGS];
            if ((t & 3) == 3)
                step2<true >(em0, em1, pp, is0, is1, E0, E1, sp[t & 1], lane, h);
            else
                step2<false>(em0, em1, pp, is0, is1, E0, E1, sp[t & 1], lane, h);
        }
        #pragma unroll
        for (int t = 512 - PF; t < 512; t++) {
            float em0 = eb0[t & (PF - 1)];
            float em1 = eb1[t & (PF - 1)];
            if ((t & 3) == 3)
                step2<true >(em0, em1, pp, is0, is1, E0, E1, sp[t & 1], lane, h);
            else
                step2<false>(em0, em1, pp, is0, is1, E0, E1, sp[t & 1], lane, h);
        }
    } else {
        #pragma unroll 2
        for (int t = 0; t < S; t++) {
            float em0 = eb0[t & (PF - 1)];
            float em1 = eb1[t & (PF - 1)];
            if (t + PF < S) {
                eb0[t & (PF - 1)] = f0[(size_t)(t + PF) * T_TAGS];
                eb1[t & (PF - 1)] = f1[(size_t)(t + PF) * T_TAGS];
            }
            if ((t & 3) == 3)
                step2<true >(em0, em1, pp, is0, is1, E0, E1, sp[t & 1], lane, h);
            else
                step2<false>(em0, em1, pp, is0, is1, E0, E1, sp[t & 1], lane, h);
        }
    }

    // ---- Termination: logZ_b = ln2 * (ishift_b + log2(sum_j p_j * estop_j)) ----
    float estop = ex2a(trans[STOP_TAG * T_TAGS + lane] * LOG2E);  // exp(-1e4)->0 ok
    unsigned long long v = mul2(pp, pk2(estop, estop));
    #pragma unroll
    for (int off = 16; off; off >>= 1)
        v = add2(v, __shfl_xor_sync(0xffffffffu, v, off));
    if (lane == 0) {
        float v0, v1;
        upk2(v, v0, v1);
        out[b0] = ((float)is0 + lg2a(v0)) * LN2;
        if (has_b1) out[b1] = ((float)is1 + lg2a(v1)) * LN2;
    }
}

extern "C" void kernel_launch(void* const* d_in, const int* in_sizes, int n_in,
                              void* d_out, int out_size) {
    const float* feats = (const float*)d_in[0];   // [B, S, 32]
    const float* trans = (const float*)d_in[1];   // [32, 32]
    float* out = (float*)d_out;                   // [B]

    const int B = out_size;
    const int S = in_sizes[0] / (B * T_TAGS);
    const int nblk = (B + 1) / 2;

    if (S == 512) {
        crf_fwd_kernel<512><<<nblk, 32>>>(feats, trans, out, S, B);
    } else {
        crf_fwd_kernel<0><<<nblk, 32>>>(feats, trans, out, S, B);
    }
}

// round 17
// speedup vs baseline: 1.5924x; 1.5924x over previous
#include <cuda_runtime.h>

// CRF forward (log partition) on GB300 — round 16.
// R14 design (all-read, no shfl in loop) with the cross-round finding applied:
// wall = S x per-warp chain latency (invariant to crossbar traffic), and the
// largest removable chain element is __syncthreads' BAR+STS-drain (~40-90cy).
// All exchange is intra-warp (1-warp CTA), so __syncwarp (~23cy) is the only
// synchronization needed; double-buffering keeps step t+1's stores from
// clobbering step t's loads.
//
// Linear-domain recurrence:
//   acc_i = sum_j E[i][j] * p_j     (16x fma.rn.f32x2 per lane, E in regs)
//   p_i   = acc_i * d_i,  d_i = exp(emit_t_i)  (one MUFU per step)
// Exact pow2 rescale every 4 steps from exponent(p[0]) (uniform across lanes,
// read from the already-loaded v0), applied off the critical path.

#define T_TAGS 32
#define START_TAG 30
#define STOP_TAG 31
#define LOG2E 1.4426950408889634f
#define LN2   0.6931471805599453f
#define PF 8   // emission prefetch depth

__device__ __forceinline__ float ex2a(float x) {
    float r; asm("ex2.approx.f32 %0, %1;" : "=f"(r) : "f"(x)); return r;
}
__device__ __forceinline__ float lg2a(float x) {
    float r; asm("lg2.approx.f32 %0, %1;" : "=f"(r) : "f"(x)); return r;
}
__device__ __forceinline__ unsigned long long pk2(float lo, float hi) {
    unsigned long long r;
    asm("mov.b64 %0, {%1, %2};" : "=l"(r) : "f"(lo), "f"(hi));
    return r;
}
__device__ __forceinline__ void upk2(unsigned long long v, float& lo, float& hi) {
    asm("mov.b64 {%0, %1}, %2;" : "=f"(lo), "=f"(hi) : "l"(v));
}
__device__ __forceinline__ unsigned long long fma2(unsigned long long a,
                                                   unsigned long long b,
                                                   unsigned long long c) {
    unsigned long long d;
    asm("fma.rn.f32x2 %0, %1, %2, %3;" : "=l"(d) : "l"(a), "l"(b), "l"(c));
    return d;
}
__device__ __forceinline__ unsigned long long add2(unsigned long long a,
                                                   unsigned long long b) {
    unsigned long long d;
    asm("add.rn.f32x2 %0, %1, %2;" : "=l"(d) : "l"(a), "l"(b));
    return d;
}

// One recurrence step. RESCALE selects the (t&3)==3 variant.
// buf is BOTH the store target and the load source for this step (syncwarp
// orders store->load; the caller alternates buffers across steps).
template <bool RESCALE>
__device__ __forceinline__ void crf_step(
    float em, float& p, int& ishift,
    const unsigned long long (&E2)[16],
    float* buf, int lane)
{
    // store FIRST — the exchange is the head of the critical chain
    buf[lane] = p;
    // d = exp(emit): MUFU issued while the syncwarp/LDS proceed
    float d = ex2a(em * LOG2E);
    __syncwarp(0xffffffffu);   // ~23cy; replaces BAR.SYNC + STS drain

    const ulonglong2* q = reinterpret_cast<const ulonglong2*>(buf);
    ulonglong2 v0 = q[0], v1 = q[1], v2 = q[2], v3 = q[3];

    float rs = 1.0f;
    if (RESCALE) {
        // exponent of p[0] (identical on all lanes) — exact pow2 shift
        float p0lo, p0hi;
        upk2(v0.x, p0lo, p0hi);
        int k = ((__float_as_int(p0lo) >> 23) & 0xff) - 127;
        ishift += k;
        rs = __int_as_float((127 - k) << 23);   // 2^-k, exact
    }

    // 16 fma2 in 4 independent chains of depth 4
    unsigned long long A, B, C, D;
    A = fma2(E2[0],  v0.x, 0ull);
    B = fma2(E2[1],  v0.y, 0ull);
    C = fma2(E2[2],  v1.x, 0ull);
    D = fma2(E2[3],  v1.y, 0ull);
    A = fma2(E2[4],  v2.x, A);
    B = fma2(E2[5],  v2.y, B);
    C = fma2(E2[6],  v3.x, C);
    D = fma2(E2[7],  v3.y, D);
    ulonglong2 w0 = q[4], w1 = q[5], w2 = q[6], w3 = q[7];
    A = fma2(E2[8],  w0.x, A);
    B = fma2(E2[9],  w0.y, B);
    C = fma2(E2[10], w1.x, C);
    D = fma2(E2[11], w1.y, D);
    A = fma2(E2[12], w2.x, A);
    B = fma2(E2[13], w2.y, B);
    C = fma2(E2[14], w3.x, C);
    D = fma2(E2[15], w3.y, D);

    unsigned long long AB = add2(A, B);
    unsigned long long CD = add2(C, D);
    unsigned long long T  = add2(AB, CD);
    float lo, hi;
    upk2(T, lo, hi);
    float acc = lo + hi;

    p = RESCALE ? acc * (d * rs) : acc * d;
}

template <int SC>
__global__ __launch_bounds__(32, 16)
void crf_fwd_kernel(const float* __restrict__ feats,
                    const float* __restrict__ trans,
                    float* __restrict__ out,
                    int S_rt) {
    const int S = (SC > 0) ? SC : S_rt;
    const int lane = threadIdx.x;
    const int b = blockIdx.x;

    __shared__ __align__(16) float sp[2][T_TAGS];

    // ---- E in registers: lane = row, 16 packed column-pairs ----
    unsigned long long E2[16];
    {
        const float* tr = trans + lane * T_TAGS;
        #pragma unroll
        for (int m = 0; m < 16; m++)
            E2[m] = pk2(ex2a(tr[2 * m] * LOG2E), ex2a(tr[2 * m + 1] * LOG2E));
    }
    // STOP-row factor for termination (exp(-1e4) -> 0, correct)
    const float estop = ex2a(trans[STOP_TAG * T_TAGS + lane] * LOG2E);

    // ---- Emission register pipeline ----
    const float* f = feats + (size_t)b * (size_t)S * T_TAGS + lane;
    float ebuf[PF];
    #pragma unroll
    for (int k = 0; k < PF; k++) ebuf[k] = f[(size_t)k * T_TAGS];

    // ---- State: p = exp(alpha - ln2*ishift), one-hot at START ----
    float p = (lane == START_TAG) ? 1.0f : 0.0f;
    int ishift = 0;

    if (SC == 512) {
        // main loop: 504 iters (63 x 8), unconditional prefetch; 8-iter tail
        #pragma unroll 8
        for (int t = 0; t < 512 - PF; t++) {
            float em = ebuf[t & (PF - 1)];
            ebuf[t & (PF - 1)] = f[(size_t)(t + PF) * T_TAGS];
            if ((t & 3) == 3)
                crf_step<true >(em, p, ishift, E2, sp[t & 1], lane);
            else
                crf_step<false>(em, p, ishift, E2, sp[t & 1], lane);
        }
        #pragma unroll
        for (int t = 512 - PF; t < 512; t++) {
            float em = ebuf[t & (PF - 1)];
            if ((t & 3) == 3)
                crf_step<true >(em, p, ishift, E2, sp[t & 1], lane);
            else
                crf_step<false>(em, p, ishift, E2, sp[t & 1], lane);
        }
    } else {
        #pragma unroll 4
        for (int t = 0; t < S; t++) {
            float em = ebuf[t & (PF - 1)];
            if (t + PF < S) ebuf[t & (PF - 1)] = f[(size_t)(t + PF) * T_TAGS];
            if ((t & 3) == 3)
                crf_step<true >(em, p, ishift, E2, sp[t & 1], lane);
            else
                crf_step<false>(em, p, ishift, E2, sp[t & 1], lane);
        }
    }

    // ---- Termination: logZ = ln2 * (ishift + log2(sum_j p_j * estop_j)) ----
    float v = p * estop;
    #pragma unroll
    for (int off = 16; off; off >>= 1)
        v += __shfl_xor_sync(0xffffffffu, v, off);
    if (lane == 0) out[b] = ((float)ishift + lg2a(v)) * LN2;
}

extern "C" void kernel_launch(void* const* d_in, const int* in_sizes, int n_in,
                              void* d_out, int out_size) {
    const float* feats = (const float*)d_in[0];   // [B, S, 32]
    const float* trans = (const float*)d_in[1];   // [32, 32]
    float* out = (float*)d_out;                   // [B]

    const int B = out_size;
    const int S = in_sizes[0] / (B * T_TAGS);

    if (S == 512) {
        crf_fwd_kernel<512><<<B, 32>>>(feats, trans, out, S);
    } else {
        crf_fwd_kernel<0><<<B, 32>>>(feats, trans, out, S);
    }
}